// round 8
// baseline (speedup 1.0000x reference)
#include <cuda_runtime.h>
#include <cuda_fp16.h>
#include <cstdint>

// ---------------- problem constants ----------------
#define NN   10000
#define FF   256
#define HH   256
#define CDIM 512                 // 2*HH fused output columns
#define BM   128
#define BN   64
#define BK   32
#define KITERS (FF / BK)         // 8  (single fp16 pass; x and W both rounded to fp16)
#define MTILES ((NN + BM - 1) / BM)  // 79
#define ASTRIDE 40               // smem row stride in halves (80B: 16B-aligned, conflict-free)
#define NSTAGE 4
#define ABYTES (BM * ASTRIDE * 2)   // 10240 per stage
#define BBYTES (BN * ASTRIDE * 2)   // 5120 per stage
#define SMEM_TOTAL (NSTAGE * (ABYTES + BBYTES) + BN * 4)   // 61696

// ---------------- scratch (allocation-free) ----------------
__device__ __half g_AB [(size_t)NN * CDIM];    // fp16 A|B rows (b1 folded into A half)
__device__ __half g_xh [(size_t)NN * FF];      // x rounded to fp16
__device__ __half g_w  [(size_t)CDIM * FF];    // combined W rows, fp16
__device__ int    g_idx64;

// ---------------- PTX helpers ----------------
__device__ __forceinline__ uint32_t smem_u32(const void* p) {
    uint32_t a;
    asm("{ .reg .u64 t; cvta.to.shared.u64 t, %1; cvt.u32.u64 %0, t; }" : "=r"(a) : "l"(p));
    return a;
}
__device__ __forceinline__ void cp_async16(uint32_t dst, const void* src, int src_sz) {
    asm volatile("cp.async.cg.shared.global [%0], [%1], 16, %2;"
                 :: "r"(dst), "l"(src), "r"(src_sz) : "memory");
}
__device__ __forceinline__ void cp_commit() { asm volatile("cp.async.commit_group;" ::: "memory"); }
template <int N>
__device__ __forceinline__ void cp_wait() { asm volatile("cp.async.wait_group %0;" :: "n"(N) : "memory"); }
__device__ __forceinline__ void ldm_x4(uint32_t& r0, uint32_t& r1, uint32_t& r2, uint32_t& r3,
                                       uint32_t addr) {
    asm volatile("ldmatrix.sync.aligned.m8n8.x4.shared.b16 {%0,%1,%2,%3}, [%4];"
                 : "=r"(r0), "=r"(r1), "=r"(r2), "=r"(r3) : "r"(addr));
}

// ---------------- prep kernels (split so launch #4 == edge kernel for ncu) ------------
#define XQ8 (NN * FF / 8)        // 320000 tasks
#define WQ8 (CDIM * FF / 8)      // 16384 tasks
__global__ void prep_x_kernel(const float* __restrict__ x) {
    const int i = blockIdx.x * blockDim.x + threadIdx.x;
    if (i >= XQ8) return;
    const int n = i >> 5, k8 = (i & 31) << 3;
    const float* sp = x + ((size_t)n << 8) + k8;
    float4 v0 = *(const float4*)sp;
    float4 v1 = *(const float4*)(sp + 4);
    __half2 h0 = __floats2half2_rn(v0.x, v0.y), h1 = __floats2half2_rn(v0.z, v0.w);
    __half2 h2 = __floats2half2_rn(v1.x, v1.y), h3 = __floats2half2_rn(v1.z, v1.w);
    *(uint4*)(g_xh + ((size_t)n << 8) + k8) =
        make_uint4(*(uint32_t*)&h0, *(uint32_t*)&h1, *(uint32_t*)&h2, *(uint32_t*)&h3);
}
__global__ void prep_w_kernel(const float* __restrict__ W1, const long long* __restrict__ ei) {
    const int i = blockIdx.x * blockDim.x + threadIdx.x;
    if (i == 0) {
        int ok = 1;
        for (int t = 0; t < 64; t++) {
            long long v = ei[t];
            if (v < 0 || v >= (long long)NN) { ok = 0; break; }
        }
        g_idx64 = ok;
    }
    if (i >= WQ8) return;
    const int c = i >> 5, k8 = (i & 31) << 3;
    const float* src = (c < HH) ? (W1 + ((size_t)c << 9) + k8)
                                : (W1 + ((size_t)(c - HH) << 9) + FF + k8);
    float4 v0 = *(const float4*)src;
    float4 v1 = *(const float4*)(src + 4);
    __half2 h0 = __floats2half2_rn(v0.x, v0.y), h1 = __floats2half2_rn(v0.z, v0.w);
    __half2 h2 = __floats2half2_rn(v1.x, v1.y), h3 = __floats2half2_rn(v1.z, v1.w);
    *(uint4*)(g_w + ((size_t)c << 8) + k8) =
        make_uint4(*(uint32_t*)&h0, *(uint32_t*)&h1, *(uint32_t*)&h2, *(uint32_t*)&h3);
}

// ---------------- phase 1: fp16 mma.sync GEMM (K=256), 4-stage pipeline -> g_AB ----------
__global__ __launch_bounds__(256, 3) void gemm_kernel(const float* __restrict__ b1) {
    extern __shared__ __align__(16) char smem[];
    float* sbias = (float*)(smem + NSTAGE * (ABYTES + BBYTES));

    const int tid = threadIdx.x, lane = tid & 31, wid = tid >> 5;
    const int wm = wid & 3, wn = wid >> 2;            // 4x2 warp grid, 32x32 each
    const int g = lane >> 2, tc = lane & 3;
    const int bm = blockIdx.x * BM;
    const int bn = blockIdx.y * BN;
    const int side = bn >> 8;

    if (tid < BN) sbias[tid] = (side == 0) ? b1[bn + tid] : 0.f;

    const int ar0 = tid >> 2,           aseg = tid & 3;
    const int ar1 = (tid + 256) >> 2;
    const int brow = tid >> 2,          bseg = tid & 3;
    const int arow0_ok = (bm + ar0) < NN ? 16 : 0;
    const int arow1_ok = (bm + ar1) < NN ? 16 : 0;
    const __half* agp0 = g_xh + ((size_t)((bm + ar0) < NN ? (bm + ar0) : 0) << 8) + aseg * 8;
    const __half* agp1 = g_xh + ((size_t)((bm + ar1) < NN ? (bm + ar1) : 0) << 8) + aseg * 8;
    const __half* bgp  = g_w + ((size_t)(bn + brow) << 8) + bseg * 8;

    const uint32_t smem_base = smem_u32(smem);
    uint32_t aS[NSTAGE], bS[NSTAGE];
    #pragma unroll
    for (int s = 0; s < NSTAGE; s++) {
        aS[s] = smem_base + s * ABYTES;
        bS[s] = smem_base + NSTAGE * ABYTES + s * BBYTES;
    }
    const uint32_t adst0 = (uint32_t)(ar0 * ASTRIDE + aseg * 8) * 2;
    const uint32_t adst1 = (uint32_t)(ar1 * ASTRIDE + aseg * 8) * 2;
    const uint32_t bdst  = (uint32_t)(brow * ASTRIDE + bseg * 8) * 2;

    const uint32_t a_loff = (uint32_t)(((wm * 32 + (lane & 15)) * ASTRIDE + (lane >> 4) * 8) * 2);
    const int b_rl = lane & 7, b_q = lane >> 3;
    const uint32_t b_loff = (uint32_t)(((wn * 32 + (b_q >> 1) * 8 + b_rl) * ASTRIDE + (b_q & 1) * 8) * 2);

    float acc[2][4][4];
    #pragma unroll
    for (int mi = 0; mi < 2; mi++)
        #pragma unroll
        for (int ni = 0; ni < 4; ni++)
            #pragma unroll
            for (int q = 0; q < 4; q++) acc[mi][ni][q] = 0.f;

    #pragma unroll
    for (int it = 0; it < NSTAGE - 1; it++) {
        const int k0 = it * BK;
        cp_async16(aS[it] + adst0, agp0 + k0, arow0_ok);
        cp_async16(aS[it] + adst1, agp1 + k0, arow1_ok);
        cp_async16(bS[it] + bdst,  bgp + k0, 16);
        cp_commit();
    }

    for (int it = 0; it < KITERS; it++) {
        cp_wait<NSTAGE - 2>();
        __syncthreads();

        {
            const int nf = it + NSTAGE - 1;
            if (nf < KITERS) {
                const int s = nf & (NSTAGE - 1);
                const int k0 = nf * BK;
                cp_async16(aS[s] + adst0, agp0 + k0, arow0_ok);
                cp_async16(aS[s] + adst1, agp1 + k0, arow1_ok);
                cp_async16(bS[s] + bdst,  bgp + k0, 16);
            }
            cp_commit();
        }

        const int s = it & (NSTAGE - 1);
        const uint32_t As = aS[s] + a_loff;
        const uint32_t Bs = bS[s] + b_loff;

        #pragma unroll
        for (int ks = 0; ks < BK; ks += 16) {
            uint32_t af[2][4], bf[4][2];
            #pragma unroll
            for (int mi = 0; mi < 2; mi++)
                ldm_x4(af[mi][0], af[mi][1], af[mi][2], af[mi][3],
                       As + (uint32_t)((mi * 16 * ASTRIDE + ks) * 2));
            #pragma unroll
            for (int p = 0; p < 2; p++)
                ldm_x4(bf[2 * p][0], bf[2 * p][1], bf[2 * p + 1][0], bf[2 * p + 1][1],
                       Bs + (uint32_t)((p * 16 * ASTRIDE + ks) * 2));
            #pragma unroll
            for (int mi = 0; mi < 2; mi++)
                #pragma unroll
                for (int ni = 0; ni < 4; ni++) {
                    float* c = acc[mi][ni];
                    asm volatile(
                        "mma.sync.aligned.m16n8k16.row.col.f32.f16.f16.f32 "
                        "{%0,%1,%2,%3}, {%4,%5,%6,%7}, {%8,%9}, {%0,%1,%2,%3};"
                        : "+f"(c[0]), "+f"(c[1]), "+f"(c[2]), "+f"(c[3])
                        : "r"(af[mi][0]), "r"(af[mi][1]), "r"(af[mi][2]), "r"(af[mi][3]),
                          "r"(bf[ni][0]), "r"(bf[ni][1]));
                }
        }
    }

    #pragma unroll
    for (int mi = 0; mi < 2; mi++) {
        const int row0 = bm + wm * 32 + mi * 16 + g;
        const int row1 = row0 + 8;
        #pragma unroll
        for (int ni = 0; ni < 4; ni++) {
            const int col = wn * 32 + ni * 8 + tc * 2;
            const float bx = sbias[col], by = sbias[col + 1];
            __half2 h0 = __floats2half2_rn(acc[mi][ni][0] + bx, acc[mi][ni][1] + by);
            __half2 h1 = __floats2half2_rn(acc[mi][ni][2] + bx, acc[mi][ni][3] + by);
            if (row0 < NN) *(__half2*)(g_AB + (size_t)row0 * CDIM + bn + col) = h0;
            if (row1 < NN) *(__half2*)(g_AB + (size_t)row1 * CDIM + bn + col) = h1;
        }
    }
}

// ---------------- phase 2: per-edge fused relu-dot-sigmoid (1 warp / edge, fp16 AB) --------
__global__ __launch_bounds__(512) void edge_kernel(const long long* __restrict__ ei,
                                                   const float* __restrict__ W2,
                                                   const float* __restrict__ b2,
                                                   float* __restrict__ out, int E) {
    const int t = threadIdx.x;
    const int e = (int)((blockIdx.x * 512u + t) >> 5);
    const int lane = t & 31;
    if (e >= E) return;

    // W2/b2 first (L1-resident broadcast) so the random AB gathers batch together
    const float4 w0 = ((const float4*)W2)[lane * 2];
    const float4 w1 = ((const float4*)W2)[lane * 2 + 1];
    const float bias2 = b2[0];

    long long r, c;
    if (g_idx64) {
        r = ei[e];
        c = ei[(size_t)E + e];
    } else {
        const int* p = (const int*)ei;
        r = p[e];
        c = p[(size_t)E + e];
    }

    const uint4 av = *((const uint4*)(g_AB + (size_t)r * CDIM) + lane);        // A cols (b1 folded)
    const uint4 bv = *((const uint4*)(g_AB + (size_t)c * CDIM + HH) + lane);   // B cols

    const __half2 z2 = __float2half2_rn(0.f);
    __half2 a0 = *(const __half2*)&av.x, a1 = *(const __half2*)&av.y,
            a2 = *(const __half2*)&av.z, a3 = *(const __half2*)&av.w;
    __half2 b0 = *(const __half2*)&bv.x, b1h = *(const __half2*)&bv.y,
            b2h = *(const __half2*)&bv.z, b3 = *(const __half2*)&bv.w;

    __half2 h0 = __hmax2(__hadd2(a0, b0), z2);
    __half2 h1 = __hmax2(__hadd2(a1, b1h), z2);
    __half2 h2 = __hmax2(__hadd2(a2, b2h), z2);
    __half2 h3 = __hmax2(__hadd2(a3, b3), z2);

    float2 f0 = __half22float2(h0), f1 = __half22float2(h1);
    float2 f2 = __half22float2(h2), f3 = __half22float2(h3);

    float acc = 0.f;
    acc = fmaf(f0.x, w0.x, acc); acc = fmaf(f0.y, w0.y, acc);
    acc = fmaf(f1.x, w0.z, acc); acc = fmaf(f1.y, w0.w, acc);
    acc = fmaf(f2.x, w1.x, acc); acc = fmaf(f2.y, w1.y, acc);
    acc = fmaf(f3.x, w1.z, acc); acc = fmaf(f3.y, w1.w, acc);

    #pragma unroll
    for (int o = 16; o > 0; o >>= 1) acc += __shfl_xor_sync(0xFFFFFFFFu, acc, o);

    if (lane == 0) {
        float z = acc + bias2;                   // TEMPERATURE = 1
        out[e] = 1.f / (1.f + __expf(-z));
    }
}

// ---------------- launch ----------------
extern "C" void kernel_launch(void* const* d_in, const int* in_sizes, int n_in,
                              void* d_out, int out_size) {
    const float*     x   = (const float*)d_in[0];
    const long long* ei  = (const long long*)d_in[1];
    const float*     W1  = (const float*)d_in[2];
    const float*     b1  = (const float*)d_in[3];
    const float*     W2  = (const float*)d_in[4];
    const float*     b2  = (const float*)d_in[5];
    float*           out = (float*)d_out;
    const int E = out_size;   // 320000

    prep_x_kernel<<<(XQ8 + 255) / 256, 256>>>(x);            // launch 1
    prep_w_kernel<<<(WQ8 + 255) / 256, 256>>>(W1, ei);       // launch 2

    cudaFuncSetAttribute(gemm_kernel, cudaFuncAttributeMaxDynamicSharedMemorySize, SMEM_TOTAL);
    dim3 ggrid(MTILES, CDIM / BN);                            // (79, 8)
    gemm_kernel<<<ggrid, 256, SMEM_TOTAL>>>(b1);              // launch 3

    int eblocks = (E + 15) / 16;                              // 16 warps/block, 1 warp/edge
    edge_kernel<<<eblocks, 512>>>(ei, W2, b2, out, E);        // launch 4  (ncu capture slot)
}

// round 9
// speedup vs baseline: 1.2210x; 1.2210x over previous
#include <cuda_runtime.h>
#include <cuda_fp16.h>
#include <cstdint>

// ---------------- problem constants ----------------
#define NN   10000
#define FF   256
#define HH   256
#define CDIM 512                 // 2*HH fused output columns
#define BM   128
#define BN   64
#define BK   32
#define KITERS (FF / BK)         // 8  (single fp16 pass; x and W both rounded to fp16)
#define MTILES ((NN + BM - 1) / BM)  // 79
#define ASTRIDE 40               // smem row stride in halves (80B: 16B-aligned, conflict-free)
#define NSTAGE 4
#define ABYTES (BM * ASTRIDE * 2)   // 10240 per stage
#define BBYTES (BN * ASTRIDE * 2)   // 5120 per stage
#define SMEM_TOTAL (NSTAGE * (ABYTES + BBYTES) + BN * 4)   // 61696
#define EPW  8                   // edges per warp in phase 2

// ---------------- scratch (allocation-free) ----------------
__device__ __half g_AB [(size_t)NN * CDIM];    // fp16 A|B rows (b1 folded into A half)
__device__ __half g_xh [(size_t)NN * FF];      // x rounded to fp16
__device__ __half g_w  [(size_t)CDIM * FF];    // combined W rows, fp16
__device__ int    g_idx64;

// ---------------- PTX helpers ----------------
__device__ __forceinline__ uint32_t smem_u32(const void* p) {
    uint32_t a;
    asm("{ .reg .u64 t; cvta.to.shared.u64 t, %1; cvt.u32.u64 %0, t; }" : "=r"(a) : "l"(p));
    return a;
}
__device__ __forceinline__ void cp_async16(uint32_t dst, const void* src, int src_sz) {
    asm volatile("cp.async.cg.shared.global [%0], [%1], 16, %2;"
                 :: "r"(dst), "l"(src), "r"(src_sz) : "memory");
}
__device__ __forceinline__ void cp_commit() { asm volatile("cp.async.commit_group;" ::: "memory"); }
template <int N>
__device__ __forceinline__ void cp_wait() { asm volatile("cp.async.wait_group %0;" :: "n"(N) : "memory"); }
__device__ __forceinline__ void ldm_x4(uint32_t& r0, uint32_t& r1, uint32_t& r2, uint32_t& r3,
                                       uint32_t addr) {
    asm volatile("ldmatrix.sync.aligned.m8n8.x4.shared.b16 {%0,%1,%2,%3}, [%4];"
                 : "=r"(r0), "=r"(r1), "=r"(r2), "=r"(r3) : "r"(addr));
}

// ---------------- prep kernels ------------
#define XQ8 (NN * FF / 8)        // 320000 tasks
#define WQ8 (CDIM * FF / 8)      // 16384 tasks
__global__ void prep_x_kernel(const float* __restrict__ x) {
    const int i = blockIdx.x * blockDim.x + threadIdx.x;
    if (i >= XQ8) return;
    const int n = i >> 5, k8 = (i & 31) << 3;
    const float* sp = x + ((size_t)n << 8) + k8;
    float4 v0 = *(const float4*)sp;
    float4 v1 = *(const float4*)(sp + 4);
    __half2 h0 = __floats2half2_rn(v0.x, v0.y), h1 = __floats2half2_rn(v0.z, v0.w);
    __half2 h2 = __floats2half2_rn(v1.x, v1.y), h3 = __floats2half2_rn(v1.z, v1.w);
    *(uint4*)(g_xh + ((size_t)n << 8) + k8) =
        make_uint4(*(uint32_t*)&h0, *(uint32_t*)&h1, *(uint32_t*)&h2, *(uint32_t*)&h3);
}
__global__ void prep_w_kernel(const float* __restrict__ W1, const long long* __restrict__ ei) {
    const int i = blockIdx.x * blockDim.x + threadIdx.x;
    if (i == 0) {
        int ok = 1;
        for (int t = 0; t < 64; t++) {
            long long v = ei[t];
            if (v < 0 || v >= (long long)NN) { ok = 0; break; }
        }
        g_idx64 = ok;
    }
    if (i >= WQ8) return;
    const int c = i >> 5, k8 = (i & 31) << 3;
    const float* src = (c < HH) ? (W1 + ((size_t)c << 9) + k8)
                                : (W1 + ((size_t)(c - HH) << 9) + FF + k8);
    float4 v0 = *(const float4*)src;
    float4 v1 = *(const float4*)(src + 4);
    __half2 h0 = __floats2half2_rn(v0.x, v0.y), h1 = __floats2half2_rn(v0.z, v0.w);
    __half2 h2 = __floats2half2_rn(v1.x, v1.y), h3 = __floats2half2_rn(v1.z, v1.w);
    *(uint4*)(g_w + ((size_t)c << 8) + k8) =
        make_uint4(*(uint32_t*)&h0, *(uint32_t*)&h1, *(uint32_t*)&h2, *(uint32_t*)&h3);
}

// ---------------- phase 1: fp16 mma.sync GEMM (K=256), 4-stage pipeline -> g_AB ----------
__global__ __launch_bounds__(256, 3) void gemm_kernel(const float* __restrict__ b1) {
    extern __shared__ __align__(16) char smem[];
    float* sbias = (float*)(smem + NSTAGE * (ABYTES + BBYTES));

    const int tid = threadIdx.x, lane = tid & 31, wid = tid >> 5;
    const int wm = wid & 3, wn = wid >> 2;            // 4x2 warp grid, 32x32 each
    const int g = lane >> 2, tc = lane & 3;
    const int bm = blockIdx.x * BM;
    const int bn = blockIdx.y * BN;
    const int side = bn >> 8;

    if (tid < BN) sbias[tid] = (side == 0) ? b1[bn + tid] : 0.f;

    const int ar0 = tid >> 2,           aseg = tid & 3;
    const int ar1 = (tid + 256) >> 2;
    const int brow = tid >> 2,          bseg = tid & 3;
    const int arow0_ok = (bm + ar0) < NN ? 16 : 0;
    const int arow1_ok = (bm + ar1) < NN ? 16 : 0;
    const __half* agp0 = g_xh + ((size_t)((bm + ar0) < NN ? (bm + ar0) : 0) << 8) + aseg * 8;
    const __half* agp1 = g_xh + ((size_t)((bm + ar1) < NN ? (bm + ar1) : 0) << 8) + aseg * 8;
    const __half* bgp  = g_w + ((size_t)(bn + brow) << 8) + bseg * 8;

    const uint32_t smem_base = smem_u32(smem);
    uint32_t aS[NSTAGE], bS[NSTAGE];
    #pragma unroll
    for (int s = 0; s < NSTAGE; s++) {
        aS[s] = smem_base + s * ABYTES;
        bS[s] = smem_base + NSTAGE * ABYTES + s * BBYTES;
    }
    const uint32_t adst0 = (uint32_t)(ar0 * ASTRIDE + aseg * 8) * 2;
    const uint32_t adst1 = (uint32_t)(ar1 * ASTRIDE + aseg * 8) * 2;
    const uint32_t bdst  = (uint32_t)(brow * ASTRIDE + bseg * 8) * 2;

    const uint32_t a_loff = (uint32_t)(((wm * 32 + (lane & 15)) * ASTRIDE + (lane >> 4) * 8) * 2);
    const int b_rl = lane & 7, b_q = lane >> 3;
    const uint32_t b_loff = (uint32_t)(((wn * 32 + (b_q >> 1) * 8 + b_rl) * ASTRIDE + (b_q & 1) * 8) * 2);

    float acc[2][4][4];
    #pragma unroll
    for (int mi = 0; mi < 2; mi++)
        #pragma unroll
        for (int ni = 0; ni < 4; ni++)
            #pragma unroll
            for (int q = 0; q < 4; q++) acc[mi][ni][q] = 0.f;

    #pragma unroll
    for (int it = 0; it < NSTAGE - 1; it++) {
        const int k0 = it * BK;
        cp_async16(aS[it] + adst0, agp0 + k0, arow0_ok);
        cp_async16(aS[it] + adst1, agp1 + k0, arow1_ok);
        cp_async16(bS[it] + bdst,  bgp + k0, 16);
        cp_commit();
    }

    for (int it = 0; it < KITERS; it++) {
        cp_wait<NSTAGE - 2>();
        __syncthreads();

        {
            const int nf = it + NSTAGE - 1;
            if (nf < KITERS) {
                const int s = nf & (NSTAGE - 1);
                const int k0 = nf * BK;
                cp_async16(aS[s] + adst0, agp0 + k0, arow0_ok);
                cp_async16(aS[s] + adst1, agp1 + k0, arow1_ok);
                cp_async16(bS[s] + bdst,  bgp + k0, 16);
            }
            cp_commit();
        }

        const int s = it & (NSTAGE - 1);
        const uint32_t As = aS[s] + a_loff;
        const uint32_t Bs = bS[s] + b_loff;

        #pragma unroll
        for (int ks = 0; ks < BK; ks += 16) {
            uint32_t af[2][4], bf[4][2];
            #pragma unroll
            for (int mi = 0; mi < 2; mi++)
                ldm_x4(af[mi][0], af[mi][1], af[mi][2], af[mi][3],
                       As + (uint32_t)((mi * 16 * ASTRIDE + ks) * 2));
            #pragma unroll
            for (int p = 0; p < 2; p++)
                ldm_x4(bf[2 * p][0], bf[2 * p][1], bf[2 * p + 1][0], bf[2 * p + 1][1],
                       Bs + (uint32_t)((p * 16 * ASTRIDE + ks) * 2));
            #pragma unroll
            for (int mi = 0; mi < 2; mi++)
                #pragma unroll
                for (int ni = 0; ni < 4; ni++) {
                    float* c = acc[mi][ni];
                    asm volatile(
                        "mma.sync.aligned.m16n8k16.row.col.f32.f16.f16.f32 "
                        "{%0,%1,%2,%3}, {%4,%5,%6,%7}, {%8,%9}, {%0,%1,%2,%3};"
                        : "+f"(c[0]), "+f"(c[1]), "+f"(c[2]), "+f"(c[3])
                        : "r"(af[mi][0]), "r"(af[mi][1]), "r"(af[mi][2]), "r"(af[mi][3]),
                          "r"(bf[ni][0]), "r"(bf[ni][1]));
                }
        }
    }

    #pragma unroll
    for (int mi = 0; mi < 2; mi++) {
        const int row0 = bm + wm * 32 + mi * 16 + g;
        const int row1 = row0 + 8;
        #pragma unroll
        for (int ni = 0; ni < 4; ni++) {
            const int col = wn * 32 + ni * 8 + tc * 2;
            const float bx = sbias[col], by = sbias[col + 1];
            __half2 h0 = __floats2half2_rn(acc[mi][ni][0] + bx, acc[mi][ni][1] + by);
            __half2 h1 = __floats2half2_rn(acc[mi][ni][2] + bx, acc[mi][ni][3] + by);
            if (row0 < NN) *(__half2*)(g_AB + (size_t)row0 * CDIM + bn + col) = h0;
            if (row1 < NN) *(__half2*)(g_AB + (size_t)row1 * CDIM + bn + col) = h1;
        }
    }
}

// ---------------- phase 2: multi-edge warps (EPW edges / warp, W2 amortized) --------------
__device__ __forceinline__ float edge_dot(const uint4 av, const uint4 bv,
                                          const float4 w0, const float4 w1) {
    const __half2 z2 = __float2half2_rn(0.f);
    __half2 a0 = *(const __half2*)&av.x, a1 = *(const __half2*)&av.y,
            a2 = *(const __half2*)&av.z, a3 = *(const __half2*)&av.w;
    __half2 b0 = *(const __half2*)&bv.x, b1h = *(const __half2*)&bv.y,
            b2h = *(const __half2*)&bv.z, b3 = *(const __half2*)&bv.w;
    __half2 h0 = __hmax2(__hadd2(a0, b0), z2);
    __half2 h1 = __hmax2(__hadd2(a1, b1h), z2);
    __half2 h2 = __hmax2(__hadd2(a2, b2h), z2);
    __half2 h3 = __hmax2(__hadd2(a3, b3), z2);
    float2 f0 = __half22float2(h0), f1 = __half22float2(h1);
    float2 f2 = __half22float2(h2), f3 = __half22float2(h3);
    float acc = 0.f;
    acc = fmaf(f0.x, w0.x, acc); acc = fmaf(f0.y, w0.y, acc);
    acc = fmaf(f1.x, w0.z, acc); acc = fmaf(f1.y, w0.w, acc);
    acc = fmaf(f2.x, w1.x, acc); acc = fmaf(f2.y, w1.y, acc);
    acc = fmaf(f3.x, w1.z, acc); acc = fmaf(f3.y, w1.w, acc);
    return acc;
}

__global__ __launch_bounds__(512) void edge_kernel(const long long* __restrict__ ei,
                                                   const float* __restrict__ W2,
                                                   const float* __restrict__ b2,
                                                   float* __restrict__ out, int E) {
    const int lane = threadIdx.x & 31;
    const int warp = (int)(blockIdx.x * 16u + (threadIdx.x >> 5));
    const int base = warp * EPW;
    if (base >= E) return;

    // W2/b2 loaded once per warp, amortized over EPW edges
    const float4 w0 = ((const float4*)W2)[lane * 2];
    const float4 w1 = ((const float4*)W2)[lane * 2 + 1];
    const float bias2 = b2[0];

    // prefetch all EPW index pairs (batched -> high MLP)
    int rr[EPW], cc[EPW];
    const bool full = (base + EPW) <= E;
    if (g_idx64) {
        if (full) {
            #pragma unroll
            for (int j = 0; j < EPW; j++) {
                rr[j] = (int)ei[base + j];
                cc[j] = (int)ei[(size_t)E + base + j];
            }
        } else {
            #pragma unroll
            for (int j = 0; j < EPW; j++) {
                const int e = base + j;
                rr[j] = (e < E) ? (int)ei[e] : 0;
                cc[j] = (e < E) ? (int)ei[(size_t)E + e] : 0;
            }
        }
    } else {
        const int* p = (const int*)ei;
        if (full) {
            #pragma unroll
            for (int j = 0; j < EPW; j++) {
                rr[j] = p[base + j];
                cc[j] = p[(size_t)E + base + j];
            }
        } else {
            #pragma unroll
            for (int j = 0; j < EPW; j++) {
                const int e = base + j;
                rr[j] = (e < E) ? p[e] : 0;
                cc[j] = (e < E) ? p[(size_t)E + e] : 0;
            }
        }
    }

    // process edges in pairs: 4 gathers in flight per step
    #pragma unroll
    for (int jj = 0; jj < EPW; jj += 2) {
        const int e0 = base + jj, e1 = base + jj + 1;
        const uint4 av0 = *((const uint4*)(g_AB + (size_t)rr[jj] * CDIM) + lane);
        const uint4 bv0 = *((const uint4*)(g_AB + (size_t)cc[jj] * CDIM + HH) + lane);
        const uint4 av1 = *((const uint4*)(g_AB + (size_t)rr[jj + 1] * CDIM) + lane);
        const uint4 bv1 = *((const uint4*)(g_AB + (size_t)cc[jj + 1] * CDIM + HH) + lane);

        float acc0 = edge_dot(av0, bv0, w0, w1);
        float acc1 = edge_dot(av1, bv1, w0, w1);

        #pragma unroll
        for (int o = 16; o > 0; o >>= 1) {
            acc0 += __shfl_xor_sync(0xFFFFFFFFu, acc0, o);
            acc1 += __shfl_xor_sync(0xFFFFFFFFu, acc1, o);
        }
        if (lane == 0 && e0 < E) out[e0] = 1.f / (1.f + __expf(-(acc0 + bias2)));
        if (lane == 1 && e1 < E) out[e1] = 1.f / (1.f + __expf(-(acc1 + bias2)));
    }
}

// ---------------- launch ----------------
extern "C" void kernel_launch(void* const* d_in, const int* in_sizes, int n_in,
                              void* d_out, int out_size) {
    const float*     x   = (const float*)d_in[0];
    const long long* ei  = (const long long*)d_in[1];
    const float*     W1  = (const float*)d_in[2];
    const float*     b1  = (const float*)d_in[3];
    const float*     W2  = (const float*)d_in[4];
    const float*     b2  = (const float*)d_in[5];
    float*           out = (float*)d_out;
    const int E = out_size;   // 320000

    prep_x_kernel<<<(XQ8 + 255) / 256, 256>>>(x);            // launch 1
    prep_w_kernel<<<(WQ8 + 255) / 256, 256>>>(W1, ei);       // launch 2

    cudaFuncSetAttribute(gemm_kernel, cudaFuncAttributeMaxDynamicSharedMemorySize, SMEM_TOTAL);
    dim3 ggrid(MTILES, CDIM / BN);                            // (79, 8)
    gemm_kernel<<<ggrid, 256, SMEM_TOTAL>>>(b1);              // launch 3

    const int warps = (E + EPW - 1) / EPW;                    // 40000
    const int eblocks = (warps + 15) / 16;                    // 2500
    edge_kernel<<<eblocks, 512>>>(ei, W2, b2, out, E);        // launch 4 (ncu capture slot)
}

// round 10
// speedup vs baseline: 1.3705x; 1.1224x over previous
#include <cuda_runtime.h>
#include <cuda_fp16.h>
#include <cstdint>

// ---------------- problem constants ----------------
#define NN   10000
#define FF   256
#define HH   256
#define CDIM 512                 // 2*HH fused output columns
#define BM   128
#define BN   64
#define BK   32
#define KITERS (FF / BK)         // 8  (single fp16 pass; x and W both rounded to fp16)
#define MTILES ((NN + BM - 1) / BM)  // 79
#define ASTRIDE 40               // smem row stride in halves (80B: 16B-aligned, conflict-free)
#define NSTAGE 4
#define ABYTES (BM * ASTRIDE * 2)   // 10240 per stage
#define BBYTES (BN * ASTRIDE * 2)   // 5120 per stage
#define SMEM_TOTAL (NSTAGE * (ABYTES + BBYTES) + BN * 4)   // 61696
#define EPW  8                   // edges per warp in phase 2

// ---------------- scratch (allocation-free) ----------------
__device__ __half g_AB [(size_t)NN * CDIM];    // fp16 A|B rows (b1 folded into A half)
__device__ __half g_xh [(size_t)NN * FF];      // x rounded to fp16
__device__ __half g_w  [(size_t)CDIM * FF];    // combined W rows, fp16
__device__ int    g_idx64;

// ---------------- PTX helpers ----------------
__device__ __forceinline__ uint32_t smem_u32(const void* p) {
    uint32_t a;
    asm("{ .reg .u64 t; cvta.to.shared.u64 t, %1; cvt.u32.u64 %0, t; }" : "=r"(a) : "l"(p));
    return a;
}
__device__ __forceinline__ void cp_async16(uint32_t dst, const void* src, int src_sz) {
    asm volatile("cp.async.cg.shared.global [%0], [%1], 16, %2;"
                 :: "r"(dst), "l"(src), "r"(src_sz) : "memory");
}
__device__ __forceinline__ void cp_commit() { asm volatile("cp.async.commit_group;" ::: "memory"); }
template <int N>
__device__ __forceinline__ void cp_wait() { asm volatile("cp.async.wait_group %0;" :: "n"(N) : "memory"); }
__device__ __forceinline__ void ldm_x4(uint32_t& r0, uint32_t& r1, uint32_t& r2, uint32_t& r3,
                                       uint32_t addr) {
    asm volatile("ldmatrix.sync.aligned.m8n8.x4.shared.b16 {%0,%1,%2,%3}, [%4];"
                 : "=r"(r0), "=r"(r1), "=r"(r2), "=r"(r3) : "r"(addr));
}

// ---------------- prep kernels ------------
#define XQ8 (NN * FF / 8)        // 320000 tasks
#define WQ8 (CDIM * FF / 8)      // 16384 tasks
__global__ void prep_x_kernel(const float* __restrict__ x) {
    const int i = blockIdx.x * blockDim.x + threadIdx.x;
    if (i >= XQ8) return;
    const int n = i >> 5, k8 = (i & 31) << 3;
    const float* sp = x + ((size_t)n << 8) + k8;
    float4 v0 = *(const float4*)sp;
    float4 v1 = *(const float4*)(sp + 4);
    __half2 h0 = __floats2half2_rn(v0.x, v0.y), h1 = __floats2half2_rn(v0.z, v0.w);
    __half2 h2 = __floats2half2_rn(v1.x, v1.y), h3 = __floats2half2_rn(v1.z, v1.w);
    *(uint4*)(g_xh + ((size_t)n << 8) + k8) =
        make_uint4(*(uint32_t*)&h0, *(uint32_t*)&h1, *(uint32_t*)&h2, *(uint32_t*)&h3);
}
__global__ void prep_w_kernel(const float* __restrict__ W1, const long long* __restrict__ ei) {
    const int i = blockIdx.x * blockDim.x + threadIdx.x;
    if (i == 0) {
        int ok = 1;
        for (int t = 0; t < 64; t++) {
            long long v = ei[t];
            if (v < 0 || v >= (long long)NN) { ok = 0; break; }
        }
        g_idx64 = ok;
    }
    if (i >= WQ8) return;
    const int c = i >> 5, k8 = (i & 31) << 3;
    const float* src = (c < HH) ? (W1 + ((size_t)c << 9) + k8)
                                : (W1 + ((size_t)(c - HH) << 9) + FF + k8);
    float4 v0 = *(const float4*)src;
    float4 v1 = *(const float4*)(src + 4);
    __half2 h0 = __floats2half2_rn(v0.x, v0.y), h1 = __floats2half2_rn(v0.z, v0.w);
    __half2 h2 = __floats2half2_rn(v1.x, v1.y), h3 = __floats2half2_rn(v1.z, v1.w);
    *(uint4*)(g_w + ((size_t)c << 8) + k8) =
        make_uint4(*(uint32_t*)&h0, *(uint32_t*)&h1, *(uint32_t*)&h2, *(uint32_t*)&h3);
}

// ---------------- phase 1: fp16 mma.sync GEMM (K=256), 4-stage pipeline -> g_AB ----------
__global__ __launch_bounds__(256, 3) void gemm_kernel(const float* __restrict__ b1) {
    extern __shared__ __align__(16) char smem[];
    float* sbias = (float*)(smem + NSTAGE * (ABYTES + BBYTES));

    const int tid = threadIdx.x, lane = tid & 31, wid = tid >> 5;
    const int wm = wid & 3, wn = wid >> 2;            // 4x2 warp grid, 32x32 each
    const int g = lane >> 2, tc = lane & 3;
    const int bm = blockIdx.x * BM;
    const int bn = blockIdx.y * BN;
    const int side = bn >> 8;

    if (tid < BN) sbias[tid] = (side == 0) ? b1[bn + tid] : 0.f;

    const int ar0 = tid >> 2,           aseg = tid & 3;
    const int ar1 = (tid + 256) >> 2;
    const int brow = tid >> 2,          bseg = tid & 3;
    const int arow0_ok = (bm + ar0) < NN ? 16 : 0;
    const int arow1_ok = (bm + ar1) < NN ? 16 : 0;
    const __half* agp0 = g_xh + ((size_t)((bm + ar0) < NN ? (bm + ar0) : 0) << 8) + aseg * 8;
    const __half* agp1 = g_xh + ((size_t)((bm + ar1) < NN ? (bm + ar1) : 0) << 8) + aseg * 8;
    const __half* bgp  = g_w + ((size_t)(bn + brow) << 8) + bseg * 8;

    const uint32_t smem_base = smem_u32(smem);
    uint32_t aS[NSTAGE], bS[NSTAGE];
    #pragma unroll
    for (int s = 0; s < NSTAGE; s++) {
        aS[s] = smem_base + s * ABYTES;
        bS[s] = smem_base + NSTAGE * ABYTES + s * BBYTES;
    }
    const uint32_t adst0 = (uint32_t)(ar0 * ASTRIDE + aseg * 8) * 2;
    const uint32_t adst1 = (uint32_t)(ar1 * ASTRIDE + aseg * 8) * 2;
    const uint32_t bdst  = (uint32_t)(brow * ASTRIDE + bseg * 8) * 2;

    const uint32_t a_loff = (uint32_t)(((wm * 32 + (lane & 15)) * ASTRIDE + (lane >> 4) * 8) * 2);
    const int b_rl = lane & 7, b_q = lane >> 3;
    const uint32_t b_loff = (uint32_t)(((wn * 32 + (b_q >> 1) * 8 + b_rl) * ASTRIDE + (b_q & 1) * 8) * 2);

    float acc[2][4][4];
    #pragma unroll
    for (int mi = 0; mi < 2; mi++)
        #pragma unroll
        for (int ni = 0; ni < 4; ni++)
            #pragma unroll
            for (int q = 0; q < 4; q++) acc[mi][ni][q] = 0.f;

    #pragma unroll
    for (int it = 0; it < NSTAGE - 1; it++) {
        const int k0 = it * BK;
        cp_async16(aS[it] + adst0, agp0 + k0, arow0_ok);
        cp_async16(aS[it] + adst1, agp1 + k0, arow1_ok);
        cp_async16(bS[it] + bdst,  bgp + k0, 16);
        cp_commit();
    }

    for (int it = 0; it < KITERS; it++) {
        cp_wait<NSTAGE - 2>();
        __syncthreads();

        {
            const int nf = it + NSTAGE - 1;
            if (nf < KITERS) {
                const int s = nf & (NSTAGE - 1);
                const int k0 = nf * BK;
                cp_async16(aS[s] + adst0, agp0 + k0, arow0_ok);
                cp_async16(aS[s] + adst1, agp1 + k0, arow1_ok);
                cp_async16(bS[s] + bdst,  bgp + k0, 16);
            }
            cp_commit();
        }

        const int s = it & (NSTAGE - 1);
        const uint32_t As = aS[s] + a_loff;
        const uint32_t Bs = bS[s] + b_loff;

        #pragma unroll
        for (int ks = 0; ks < BK; ks += 16) {
            uint32_t af[2][4], bf[4][2];
            #pragma unroll
            for (int mi = 0; mi < 2; mi++)
                ldm_x4(af[mi][0], af[mi][1], af[mi][2], af[mi][3],
                       As + (uint32_t)((mi * 16 * ASTRIDE + ks) * 2));
            #pragma unroll
            for (int p = 0; p < 2; p++)
                ldm_x4(bf[2 * p][0], bf[2 * p][1], bf[2 * p + 1][0], bf[2 * p + 1][1],
                       Bs + (uint32_t)((p * 16 * ASTRIDE + ks) * 2));
            #pragma unroll
            for (int mi = 0; mi < 2; mi++)
                #pragma unroll
                for (int ni = 0; ni < 4; ni++) {
                    float* c = acc[mi][ni];
                    asm volatile(
                        "mma.sync.aligned.m16n8k16.row.col.f32.f16.f16.f32 "
                        "{%0,%1,%2,%3}, {%4,%5,%6,%7}, {%8,%9}, {%0,%1,%2,%3};"
                        : "+f"(c[0]), "+f"(c[1]), "+f"(c[2]), "+f"(c[3])
                        : "r"(af[mi][0]), "r"(af[mi][1]), "r"(af[mi][2]), "r"(af[mi][3]),
                          "r"(bf[ni][0]), "r"(bf[ni][1]));
                }
        }
    }

    #pragma unroll
    for (int mi = 0; mi < 2; mi++) {
        const int row0 = bm + wm * 32 + mi * 16 + g;
        const int row1 = row0 + 8;
        #pragma unroll
        for (int ni = 0; ni < 4; ni++) {
            const int col = wn * 32 + ni * 8 + tc * 2;
            const float bx = sbias[col], by = sbias[col + 1];
            __half2 h0 = __floats2half2_rn(acc[mi][ni][0] + bx, acc[mi][ni][1] + by);
            __half2 h1 = __floats2half2_rn(acc[mi][ni][2] + bx, acc[mi][ni][3] + by);
            if (row0 < NN) *(__half2*)(g_AB + (size_t)row0 * CDIM + bn + col) = h0;
            if (row1 < NN) *(__half2*)(g_AB + (size_t)row1 * CDIM + bn + col) = h1;
        }
    }
}

// ---------------- phase 2: multi-edge warps, lane-staged indices, 256-thread blocks -------
__device__ __forceinline__ float edge_dot(const uint4 av, const uint4 bv,
                                          const float4 w0, const float4 w1) {
    const __half2 z2 = __float2half2_rn(0.f);
    __half2 a0 = *(const __half2*)&av.x, a1 = *(const __half2*)&av.y,
            a2 = *(const __half2*)&av.z, a3 = *(const __half2*)&av.w;
    __half2 b0 = *(const __half2*)&bv.x, b1h = *(const __half2*)&bv.y,
            b2h = *(const __half2*)&bv.z, b3 = *(const __half2*)&bv.w;
    __half2 h0 = __hmax2(__hadd2(a0, b0), z2);
    __half2 h1 = __hmax2(__hadd2(a1, b1h), z2);
    __half2 h2 = __hmax2(__hadd2(a2, b2h), z2);
    __half2 h3 = __hmax2(__hadd2(a3, b3), z2);
    float2 f0 = __half22float2(h0), f1 = __half22float2(h1);
    float2 f2 = __half22float2(h2), f3 = __half22float2(h3);
    float acc = 0.f;
    acc = fmaf(f0.x, w0.x, acc); acc = fmaf(f0.y, w0.y, acc);
    acc = fmaf(f1.x, w0.z, acc); acc = fmaf(f1.y, w0.w, acc);
    acc = fmaf(f2.x, w1.x, acc); acc = fmaf(f2.y, w1.y, acc);
    acc = fmaf(f3.x, w1.z, acc); acc = fmaf(f3.y, w1.w, acc);
    return acc;
}

__global__ __launch_bounds__(256) void edge_kernel(const long long* __restrict__ ei,
                                                   const float* __restrict__ W2,
                                                   const float* __restrict__ b2,
                                                   float* __restrict__ out, int E) {
    const int lane = threadIdx.x & 31;
    const int warp = (int)(blockIdx.x * 8u + (threadIdx.x >> 5));
    const int base = warp * EPW;
    if (base >= E) return;

    const float4 w0 = ((const float4*)W2)[lane * 2];
    const float4 w1 = ((const float4*)W2)[lane * 2 + 1];
    const float bias2 = b2[0];

    // lane-staged indices: lanes 0-7 hold r[0..7], lanes 8-15 hold c[0..7]
    int myidx = 0;
    {
        const int j = lane & 7;
        const int e = base + j;
        const bool want = (lane < 16) && (e < E);
        if (g_idx64) {
            if (want) myidx = (int)ei[(lane < 8 ? (size_t)0 : (size_t)E) + e];
        } else {
            const int* p = (const int*)ei;
            if (want) myidx = p[(lane < 8 ? (size_t)0 : (size_t)E) + e];
        }
    }

    #pragma unroll
    for (int jj = 0; jj < EPW; jj += 2) {
        const int e0 = base + jj, e1 = base + jj + 1;
        const int r0 = __shfl_sync(0xFFFFFFFFu, myidx, jj);
        const int c0 = __shfl_sync(0xFFFFFFFFu, myidx, jj + 8);
        const int r1 = __shfl_sync(0xFFFFFFFFu, myidx, jj + 1);
        const int c1 = __shfl_sync(0xFFFFFFFFu, myidx, jj + 9);

        const uint4 av0 = *((const uint4*)(g_AB + (size_t)r0 * CDIM) + lane);
        const uint4 bv0 = *((const uint4*)(g_AB + (size_t)c0 * CDIM + HH) + lane);
        const uint4 av1 = *((const uint4*)(g_AB + (size_t)r1 * CDIM) + lane);
        const uint4 bv1 = *((const uint4*)(g_AB + (size_t)c1 * CDIM + HH) + lane);

        float acc0 = edge_dot(av0, bv0, w0, w1);
        float acc1 = edge_dot(av1, bv1, w0, w1);

        #pragma unroll
        for (int o = 16; o > 0; o >>= 1) {
            acc0 += __shfl_xor_sync(0xFFFFFFFFu, acc0, o);
            acc1 += __shfl_xor_sync(0xFFFFFFFFu, acc1, o);
        }
        if (lane == 0 && e0 < E) out[e0] = 1.f / (1.f + __expf(-(acc0 + bias2)));
        if (lane == 1 && e1 < E) out[e1] = 1.f / (1.f + __expf(-(acc1 + bias2)));
    }
}

// ---------------- launch ----------------
extern "C" void kernel_launch(void* const* d_in, const int* in_sizes, int n_in,
                              void* d_out, int out_size) {
    const float*     x   = (const float*)d_in[0];
    const long long* ei  = (const long long*)d_in[1];
    const float*     W1  = (const float*)d_in[2];
    const float*     b1  = (const float*)d_in[3];
    const float*     W2  = (const float*)d_in[4];
    const float*     b2  = (const float*)d_in[5];
    float*           out = (float*)d_out;
    const int E = out_size;   // 320000

    prep_x_kernel<<<(XQ8 + 255) / 256, 256>>>(x);            // launch 1
    prep_w_kernel<<<(WQ8 + 255) / 256, 256>>>(W1, ei);       // launch 2

    cudaFuncSetAttribute(gemm_kernel, cudaFuncAttributeMaxDynamicSharedMemorySize, SMEM_TOTAL);
    dim3 ggrid(MTILES, CDIM / BN);                            // (79, 8)
    gemm_kernel<<<ggrid, 256, SMEM_TOTAL>>>(b1);              // launch 3

    const int warps = (E + EPW - 1) / EPW;                    // 40000
    const int eblocks = (warps + 7) / 8;                      // 5000
    edge_kernel<<<eblocks, 256>>>(ei, W2, b2, out, E);        // launch 4 (ncu capture slot)
}

// round 11
// speedup vs baseline: 1.4294x; 1.0430x over previous
#include <cuda_runtime.h>
#include <cuda_fp16.h>
#include <cstdint>

// ---------------- problem constants ----------------
#define NN   10000
#define FF   256
#define HH   256
#define CDIM 512                 // 2*HH fused output columns
#define BM   128
#define BN   64
#define BK   32
#define KITERS (FF / BK)         // 8  (single fp16 pass; x and W both rounded to fp16)
#define MTILES ((NN + BM - 1) / BM)  // 79
#define ASTRIDE 40               // smem row stride in halves (80B: 16B-aligned, conflict-free)
#define NSTAGE 4
#define ABYTES (BM * ASTRIDE * 2)   // 10240 per stage
#define BBYTES (BN * ASTRIDE * 2)   // 5120 per stage
#define SMEM_TOTAL (NSTAGE * (ABYTES + BBYTES) + BN * 4)   // 61696
#define EPW  8                   // edges per warp in phase 2

// ---------------- scratch (allocation-free) ----------------
__device__ __half g_AB [(size_t)NN * CDIM];    // fp16 A|B rows (b1 folded into A half)
__device__ __half g_xh [(size_t)NN * FF];      // x rounded to fp16
__device__ __half g_w  [(size_t)CDIM * FF];    // combined W rows, fp16
__device__ int    g_idx64;

// ---------------- PTX helpers ----------------
__device__ __forceinline__ uint32_t smem_u32(const void* p) {
    uint32_t a;
    asm("{ .reg .u64 t; cvta.to.shared.u64 t, %1; cvt.u32.u64 %0, t; }" : "=r"(a) : "l"(p));
    return a;
}
__device__ __forceinline__ void cp_async16(uint32_t dst, const void* src, int src_sz) {
    asm volatile("cp.async.cg.shared.global [%0], [%1], 16, %2;"
                 :: "r"(dst), "l"(src), "r"(src_sz) : "memory");
}
__device__ __forceinline__ void cp_commit() { asm volatile("cp.async.commit_group;" ::: "memory"); }
template <int N>
__device__ __forceinline__ void cp_wait() { asm volatile("cp.async.wait_group %0;" :: "n"(N) : "memory"); }
__device__ __forceinline__ void ldm_x4(uint32_t& r0, uint32_t& r1, uint32_t& r2, uint32_t& r3,
                                       uint32_t addr) {
    asm volatile("ldmatrix.sync.aligned.m8n8.x4.shared.b16 {%0,%1,%2,%3}, [%4];"
                 : "=r"(r0), "=r"(r1), "=r"(r2), "=r"(r3) : "r"(addr));
}

// ---------------- prep kernels ------------
#define XQ8 (NN * FF / 8)        // 320000 tasks
#define WQ8 (CDIM * FF / 8)      // 16384 tasks
__global__ void prep_x_kernel(const float* __restrict__ x) {
    const int i = blockIdx.x * blockDim.x + threadIdx.x;
    if (i >= XQ8) return;
    const int n = i >> 5, k8 = (i & 31) << 3;
    const float* sp = x + ((size_t)n << 8) + k8;
    float4 v0 = *(const float4*)sp;
    float4 v1 = *(const float4*)(sp + 4);
    __half2 h0 = __floats2half2_rn(v0.x, v0.y), h1 = __floats2half2_rn(v0.z, v0.w);
    __half2 h2 = __floats2half2_rn(v1.x, v1.y), h3 = __floats2half2_rn(v1.z, v1.w);
    *(uint4*)(g_xh + ((size_t)n << 8) + k8) =
        make_uint4(*(uint32_t*)&h0, *(uint32_t*)&h1, *(uint32_t*)&h2, *(uint32_t*)&h3);
}
__global__ void prep_w_kernel(const float* __restrict__ W1, const long long* __restrict__ ei) {
    const int i = blockIdx.x * blockDim.x + threadIdx.x;
    if (i == 0) {
        int ok = 1;
        for (int t = 0; t < 64; t++) {
            long long v = ei[t];
            if (v < 0 || v >= (long long)NN) { ok = 0; break; }
        }
        g_idx64 = ok;
    }
    if (i >= WQ8) return;
    const int c = i >> 5, k8 = (i & 31) << 3;
    const float* src = (c < HH) ? (W1 + ((size_t)c << 9) + k8)
                                : (W1 + ((size_t)(c - HH) << 9) + FF + k8);
    float4 v0 = *(const float4*)src;
    float4 v1 = *(const float4*)(src + 4);
    __half2 h0 = __floats2half2_rn(v0.x, v0.y), h1 = __floats2half2_rn(v0.z, v0.w);
    __half2 h2 = __floats2half2_rn(v1.x, v1.y), h3 = __floats2half2_rn(v1.z, v1.w);
    *(uint4*)(g_w + ((size_t)c << 8) + k8) =
        make_uint4(*(uint32_t*)&h0, *(uint32_t*)&h1, *(uint32_t*)&h2, *(uint32_t*)&h3);
}

// ---------------- phase 1: fp16 mma.sync GEMM (K=256), 4-stage pipeline -> g_AB ----------
__global__ __launch_bounds__(256, 3) void gemm_kernel(const float* __restrict__ b1) {
    extern __shared__ __align__(16) char smem[];
    float* sbias = (float*)(smem + NSTAGE * (ABYTES + BBYTES));

    const int tid = threadIdx.x, lane = tid & 31, wid = tid >> 5;
    const int wm = wid & 3, wn = wid >> 2;            // 4x2 warp grid, 32x32 each
    const int g = lane >> 2, tc = lane & 3;
    const int bm = blockIdx.x * BM;
    const int bn = blockIdx.y * BN;
    const int side = bn >> 8;

    if (tid < BN) sbias[tid] = (side == 0) ? b1[bn + tid] : 0.f;

    const int ar0 = tid >> 2,           aseg = tid & 3;
    const int ar1 = (tid + 256) >> 2;
    const int brow = tid >> 2,          bseg = tid & 3;
    const int arow0_ok = (bm + ar0) < NN ? 16 : 0;
    const int arow1_ok = (bm + ar1) < NN ? 16 : 0;
    const __half* agp0 = g_xh + ((size_t)((bm + ar0) < NN ? (bm + ar0) : 0) << 8) + aseg * 8;
    const __half* agp1 = g_xh + ((size_t)((bm + ar1) < NN ? (bm + ar1) : 0) << 8) + aseg * 8;
    const __half* bgp  = g_w + ((size_t)(bn + brow) << 8) + bseg * 8;

    const uint32_t smem_base = smem_u32(smem);
    uint32_t aS[NSTAGE], bS[NSTAGE];
    #pragma unroll
    for (int s = 0; s < NSTAGE; s++) {
        aS[s] = smem_base + s * ABYTES;
        bS[s] = smem_base + NSTAGE * ABYTES + s * BBYTES;
    }
    const uint32_t adst0 = (uint32_t)(ar0 * ASTRIDE + aseg * 8) * 2;
    const uint32_t adst1 = (uint32_t)(ar1 * ASTRIDE + aseg * 8) * 2;
    const uint32_t bdst  = (uint32_t)(brow * ASTRIDE + bseg * 8) * 2;

    const uint32_t a_loff = (uint32_t)(((wm * 32 + (lane & 15)) * ASTRIDE + (lane >> 4) * 8) * 2);
    const int b_rl = lane & 7, b_q = lane >> 3;
    const uint32_t b_loff = (uint32_t)(((wn * 32 + (b_q >> 1) * 8 + b_rl) * ASTRIDE + (b_q & 1) * 8) * 2);

    float acc[2][4][4];
    #pragma unroll
    for (int mi = 0; mi < 2; mi++)
        #pragma unroll
        for (int ni = 0; ni < 4; ni++)
            #pragma unroll
            for (int q = 0; q < 4; q++) acc[mi][ni][q] = 0.f;

    #pragma unroll
    for (int it = 0; it < NSTAGE - 1; it++) {
        const int k0 = it * BK;
        cp_async16(aS[it] + adst0, agp0 + k0, arow0_ok);
        cp_async16(aS[it] + adst1, agp1 + k0, arow1_ok);
        cp_async16(bS[it] + bdst,  bgp + k0, 16);
        cp_commit();
    }

    for (int it = 0; it < KITERS; it++) {
        cp_wait<NSTAGE - 2>();
        __syncthreads();

        {
            const int nf = it + NSTAGE - 1;
            if (nf < KITERS) {
                const int s = nf & (NSTAGE - 1);
                const int k0 = nf * BK;
                cp_async16(aS[s] + adst0, agp0 + k0, arow0_ok);
                cp_async16(aS[s] + adst1, agp1 + k0, arow1_ok);
                cp_async16(bS[s] + bdst,  bgp + k0, 16);
            }
            cp_commit();
        }

        const int s = it & (NSTAGE - 1);
        const uint32_t As = aS[s] + a_loff;
        const uint32_t Bs = bS[s] + b_loff;

        #pragma unroll
        for (int ks = 0; ks < BK; ks += 16) {
            uint32_t af[2][4], bf[4][2];
            #pragma unroll
            for (int mi = 0; mi < 2; mi++)
                ldm_x4(af[mi][0], af[mi][1], af[mi][2], af[mi][3],
                       As + (uint32_t)((mi * 16 * ASTRIDE + ks) * 2));
            #pragma unroll
            for (int p = 0; p < 2; p++)
                ldm_x4(bf[2 * p][0], bf[2 * p][1], bf[2 * p + 1][0], bf[2 * p + 1][1],
                       Bs + (uint32_t)((p * 16 * ASTRIDE + ks) * 2));
            #pragma unroll
            for (int mi = 0; mi < 2; mi++)
                #pragma unroll
                for (int ni = 0; ni < 4; ni++) {
                    float* c = acc[mi][ni];
                    asm volatile(
                        "mma.sync.aligned.m16n8k16.row.col.f32.f16.f16.f32 "
                        "{%0,%1,%2,%3}, {%4,%5,%6,%7}, {%8,%9}, {%0,%1,%2,%3};"
                        : "+f"(c[0]), "+f"(c[1]), "+f"(c[2]), "+f"(c[3])
                        : "r"(af[mi][0]), "r"(af[mi][1]), "r"(af[mi][2]), "r"(af[mi][3]),
                          "r"(bf[ni][0]), "r"(bf[ni][1]));
                }
        }
    }

    #pragma unroll
    for (int mi = 0; mi < 2; mi++) {
        const int row0 = bm + wm * 32 + mi * 16 + g;
        const int row1 = row0 + 8;
        #pragma unroll
        for (int ni = 0; ni < 4; ni++) {
            const int col = wn * 32 + ni * 8 + tc * 2;
            const float bx = sbias[col], by = sbias[col + 1];
            __half2 h0 = __floats2half2_rn(acc[mi][ni][0] + bx, acc[mi][ni][1] + by);
            __half2 h1 = __floats2half2_rn(acc[mi][ni][2] + bx, acc[mi][ni][3] + by);
            if (row0 < NN) *(__half2*)(g_AB + (size_t)row0 * CDIM + bn + col) = h0;
            if (row1 < NN) *(__half2*)(g_AB + (size_t)row1 * CDIM + bn + col) = h1;
        }
    }
}

// ---------------- phase 2: multi-edge warps, staged byte-offsets, joint reductions --------
__device__ __forceinline__ float edge_dot(const uint4 av, const uint4 bv,
                                          const float4 w0, const float4 w1) {
    const __half2 z2 = __float2half2_rn(0.f);
    __half2 a0 = *(const __half2*)&av.x, a1 = *(const __half2*)&av.y,
            a2 = *(const __half2*)&av.z, a3 = *(const __half2*)&av.w;
    __half2 b0 = *(const __half2*)&bv.x, b1h = *(const __half2*)&bv.y,
            b2h = *(const __half2*)&bv.z, b3 = *(const __half2*)&bv.w;
    __half2 h0 = __hmax2(__hadd2(a0, b0), z2);
    __half2 h1 = __hmax2(__hadd2(a1, b1h), z2);
    __half2 h2 = __hmax2(__hadd2(a2, b2h), z2);
    __half2 h3 = __hmax2(__hadd2(a3, b3), z2);
    float2 f0 = __half22float2(h0), f1 = __half22float2(h1);
    float2 f2 = __half22float2(h2), f3 = __half22float2(h3);
    // two independent FMA chains (shorter critical path), then join
    float accA = f0.x * w0.x;
    float accB = f0.y * w0.y;
    accA = fmaf(f1.x, w0.z, accA);
    accB = fmaf(f1.y, w0.w, accB);
    accA = fmaf(f2.x, w1.x, accA);
    accB = fmaf(f2.y, w1.y, accB);
    accA = fmaf(f3.x, w1.z, accA);
    accB = fmaf(f3.y, w1.w, accB);
    return accA + accB;
}

__global__ __launch_bounds__(256) void edge_kernel(const long long* __restrict__ ei,
                                                   const float* __restrict__ W2,
                                                   const float* __restrict__ b2,
                                                   float* __restrict__ out, int E) {
    const int lane = threadIdx.x & 31;
    const int warp = (int)(blockIdx.x * 8u + (threadIdx.x >> 5));
    const int base = warp * EPW;
    if (base >= E) return;

    const float4 w0 = ((const float4*)W2)[lane * 2];
    const float4 w1 = ((const float4*)W2)[lane * 2 + 1];
    const float bias2 = b2[0];

    // staged byte offsets: lanes 0-7 hold r[j]*1024; lanes 8-15 hold c[j]*1024 + 512
    uint32_t myoff = 0;
    {
        const int j = lane & 7;
        const int e = base + j;
        const bool want = (lane < 16) && (e < E);
        int idx = 0;
        if (g_idx64) {
            if (want) idx = (int)ei[(lane < 8 ? (size_t)0 : (size_t)E) + e];
        } else {
            const int* p = (const int*)ei;
            if (want) idx = p[(lane < 8 ? (size_t)0 : (size_t)E) + e];
        }
        myoff = ((uint32_t)idx << 10) + (lane < 8 ? 0u : 512u);
    }
    const char* abbase = (const char*)g_AB + lane * 16;   // per-lane fixed base

    #pragma unroll
    for (int jj = 0; jj < EPW; jj += 2) {
        const int e0 = base + jj, e1 = base + jj + 1;
        const uint32_t oa0 = __shfl_sync(0xFFFFFFFFu, myoff, jj);
        const uint32_t ob0 = __shfl_sync(0xFFFFFFFFu, myoff, jj + 8);
        const uint32_t oa1 = __shfl_sync(0xFFFFFFFFu, myoff, jj + 1);
        const uint32_t ob1 = __shfl_sync(0xFFFFFFFFu, myoff, jj + 9);

        const uint4 av0 = *(const uint4*)(abbase + oa0);
        const uint4 bv0 = *(const uint4*)(abbase + ob0);
        const uint4 av1 = *(const uint4*)(abbase + oa1);
        const uint4 bv1 = *(const uint4*)(abbase + ob1);

        float acc0 = edge_dot(av0, bv0, w0, w1);
        float acc1 = edge_dot(av1, bv1, w0, w1);

        // joint reduction: one value per lane carries acc0 (lanes<16) / acc1 (lanes>=16)
        float u     = (lane < 16) ? acc0 : acc1;
        float other = (lane < 16) ? acc1 : acc0;
        u += __shfl_xor_sync(0xFFFFFFFFu, other, 16);
        #pragma unroll
        for (int o = 8; o > 0; o >>= 1) u += __shfl_xor_sync(0xFFFFFFFFu, u, o);
        // lane 0 holds sum(acc0), lane 16 holds sum(acc1)

        if (lane == 0 && e0 < E)  out[e0] = 1.f / (1.f + __expf(-(u + bias2)));
        if (lane == 16 && e1 < E) out[e1] = 1.f / (1.f + __expf(-(u + bias2)));
    }
}

// ---------------- launch ----------------
extern "C" void kernel_launch(void* const* d_in, const int* in_sizes, int n_in,
                              void* d_out, int out_size) {
    const float*     x   = (const float*)d_in[0];
    const long long* ei  = (const long long*)d_in[1];
    const float*     W1  = (const float*)d_in[2];
    const float*     b1  = (const float*)d_in[3];
    const float*     W2  = (const float*)d_in[4];
    const float*     b2  = (const float*)d_in[5];
    float*           out = (float*)d_out;
    const int E = out_size;   // 320000

    prep_x_kernel<<<(XQ8 + 255) / 256, 256>>>(x);            // launch 1
    prep_w_kernel<<<(WQ8 + 255) / 256, 256>>>(W1, ei);       // launch 2

    cudaFuncSetAttribute(gemm_kernel, cudaFuncAttributeMaxDynamicSharedMemorySize, SMEM_TOTAL);
    dim3 ggrid(MTILES, CDIM / BN);                            // (79, 8)
    gemm_kernel<<<ggrid, 256, SMEM_TOTAL>>>(b1);              // launch 3

    const int warps = (E + EPW - 1) / EPW;                    // 40000
    const int eblocks = (warps + 7) / 8;                      // 5000
    edge_kernel<<<eblocks, 256>>>(ei, W2, b2, out, E);        // launch 4 (ncu capture slot)
}

// round 12
// speedup vs baseline: 1.5324x; 1.0720x over previous
#include <cuda_runtime.h>
#include <cuda_fp16.h>
#include <cstdint>

// ---------------- problem constants ----------------
#define NN   10000
#define FF   256
#define HH   256
#define CDIM 512                 // 2*HH fused output columns
#define BM   128
#define BN   64
#define BK   32
#define KITERS (FF / BK)         // 8  (single fp16 pass; x and W both rounded to fp16)
#define MTILES ((NN + BM - 1) / BM)  // 79
#define ASTRIDE 40               // smem row stride in halves (80B: 16B-aligned, conflict-free)
#define NSTAGE 4
#define ABYTES (BM * ASTRIDE * 2)   // 10240 per stage
#define BBYTES (BN * ASTRIDE * 2)   // 5120 per stage
#define SMEM_TOTAL (NSTAGE * (ABYTES + BBYTES) + BN * 4)   // 61696
#define EPW  8                   // edges per warp in phase 2

// ---------------- scratch (allocation-free) ----------------
__device__ __half  g_AB [(size_t)NN * CDIM];   // fp16 A|B rows (b1 folded into A half)
__device__ __half  g_xh [(size_t)NN * FF];     // x rounded to fp16
__device__ __half  g_w  [(size_t)CDIM * FF];   // combined W rows, fp16
__device__ __half2 g_w2h[HH / 2];              // W2 rounded to fp16
__device__ int     g_idx64;

// ---------------- PTX helpers ----------------
__device__ __forceinline__ uint32_t smem_u32(const void* p) {
    uint32_t a;
    asm("{ .reg .u64 t; cvta.to.shared.u64 t, %1; cvt.u32.u64 %0, t; }" : "=r"(a) : "l"(p));
    return a;
}
__device__ __forceinline__ void cp_async16(uint32_t dst, const void* src, int src_sz) {
    asm volatile("cp.async.cg.shared.global [%0], [%1], 16, %2;"
                 :: "r"(dst), "l"(src), "r"(src_sz) : "memory");
}
__device__ __forceinline__ void cp_commit() { asm volatile("cp.async.commit_group;" ::: "memory"); }
template <int N>
__device__ __forceinline__ void cp_wait() { asm volatile("cp.async.wait_group %0;" :: "n"(N) : "memory"); }
__device__ __forceinline__ void ldm_x4(uint32_t& r0, uint32_t& r1, uint32_t& r2, uint32_t& r3,
                                       uint32_t addr) {
    asm volatile("ldmatrix.sync.aligned.m8n8.x4.shared.b16 {%0,%1,%2,%3}, [%4];"
                 : "=r"(r0), "=r"(r1), "=r"(r2), "=r"(r3) : "r"(addr));
}

// ---------------- prep kernels ------------
#define XQ8 (NN * FF / 8)        // 320000 tasks
#define WQ8 (CDIM * FF / 8)      // 16384 tasks
__global__ void prep_x_kernel(const float* __restrict__ x) {
    const int i = blockIdx.x * blockDim.x + threadIdx.x;
    if (i >= XQ8) return;
    const int n = i >> 5, k8 = (i & 31) << 3;
    const float* sp = x + ((size_t)n << 8) + k8;
    float4 v0 = *(const float4*)sp;
    float4 v1 = *(const float4*)(sp + 4);
    __half2 h0 = __floats2half2_rn(v0.x, v0.y), h1 = __floats2half2_rn(v0.z, v0.w);
    __half2 h2 = __floats2half2_rn(v1.x, v1.y), h3 = __floats2half2_rn(v1.z, v1.w);
    *(uint4*)(g_xh + ((size_t)n << 8) + k8) =
        make_uint4(*(uint32_t*)&h0, *(uint32_t*)&h1, *(uint32_t*)&h2, *(uint32_t*)&h3);
}
__global__ void prep_w_kernel(const float* __restrict__ W1, const long long* __restrict__ ei,
                              const float* __restrict__ W2) {
    const int i = blockIdx.x * blockDim.x + threadIdx.x;
    if (i == 0) {
        int ok = 1;
        for (int t = 0; t < 64; t++) {
            long long v = ei[t];
            if (v < 0 || v >= (long long)NN) { ok = 0; break; }
        }
        g_idx64 = ok;
    }
    if (i < HH / 2) {
        float2 v = ((const float2*)W2)[i];
        g_w2h[i] = __floats2half2_rn(v.x, v.y);
    }
    if (i >= WQ8) return;
    const int c = i >> 5, k8 = (i & 31) << 3;
    const float* src = (c < HH) ? (W1 + ((size_t)c << 9) + k8)
                                : (W1 + ((size_t)(c - HH) << 9) + FF + k8);
    float4 v0 = *(const float4*)src;
    float4 v1 = *(const float4*)(src + 4);
    __half2 h0 = __floats2half2_rn(v0.x, v0.y), h1 = __floats2half2_rn(v0.z, v0.w);
    __half2 h2 = __floats2half2_rn(v1.x, v1.y), h3 = __floats2half2_rn(v1.z, v1.w);
    *(uint4*)(g_w + ((size_t)c << 8) + k8) =
        make_uint4(*(uint32_t*)&h0, *(uint32_t*)&h1, *(uint32_t*)&h2, *(uint32_t*)&h3);
}

// ---------------- phase 1: fp16 mma.sync GEMM (K=256), 4-stage pipeline -> g_AB ----------
__global__ __launch_bounds__(256, 3) void gemm_kernel(const float* __restrict__ b1) {
    extern __shared__ __align__(16) char smem[];
    float* sbias = (float*)(smem + NSTAGE * (ABYTES + BBYTES));

    const int tid = threadIdx.x, lane = tid & 31, wid = tid >> 5;
    const int wm = wid & 3, wn = wid >> 2;            // 4x2 warp grid, 32x32 each
    const int g = lane >> 2, tc = lane & 3;
    const int bm = blockIdx.x * BM;
    const int bn = blockIdx.y * BN;
    const int side = bn >> 8;

    if (tid < BN) sbias[tid] = (side == 0) ? b1[bn + tid] : 0.f;

    const int ar0 = tid >> 2,           aseg = tid & 3;
    const int ar1 = (tid + 256) >> 2;
    const int brow = tid >> 2,          bseg = tid & 3;
    const int arow0_ok = (bm + ar0) < NN ? 16 : 0;
    const int arow1_ok = (bm + ar1) < NN ? 16 : 0;
    const __half* agp0 = g_xh + ((size_t)((bm + ar0) < NN ? (bm + ar0) : 0) << 8) + aseg * 8;
    const __half* agp1 = g_xh + ((size_t)((bm + ar1) < NN ? (bm + ar1) : 0) << 8) + aseg * 8;
    const __half* bgp  = g_w + ((size_t)(bn + brow) << 8) + bseg * 8;

    const uint32_t smem_base = smem_u32(smem);
    uint32_t aS[NSTAGE], bS[NSTAGE];
    #pragma unroll
    for (int s = 0; s < NSTAGE; s++) {
        aS[s] = smem_base + s * ABYTES;
        bS[s] = smem_base + NSTAGE * ABYTES + s * BBYTES;
    }
    const uint32_t adst0 = (uint32_t)(ar0 * ASTRIDE + aseg * 8) * 2;
    const uint32_t adst1 = (uint32_t)(ar1 * ASTRIDE + aseg * 8) * 2;
    const uint32_t bdst  = (uint32_t)(brow * ASTRIDE + bseg * 8) * 2;

    const uint32_t a_loff = (uint32_t)(((wm * 32 + (lane & 15)) * ASTRIDE + (lane >> 4) * 8) * 2);
    const int b_rl = lane & 7, b_q = lane >> 3;
    const uint32_t b_loff = (uint32_t)(((wn * 32 + (b_q >> 1) * 8 + b_rl) * ASTRIDE + (b_q & 1) * 8) * 2);

    float acc[2][4][4];
    #pragma unroll
    for (int mi = 0; mi < 2; mi++)
        #pragma unroll
        for (int ni = 0; ni < 4; ni++)
            #pragma unroll
            for (int q = 0; q < 4; q++) acc[mi][ni][q] = 0.f;

    #pragma unroll
    for (int it = 0; it < NSTAGE - 1; it++) {
        const int k0 = it * BK;
        cp_async16(aS[it] + adst0, agp0 + k0, arow0_ok);
        cp_async16(aS[it] + adst1, agp1 + k0, arow1_ok);
        cp_async16(bS[it] + bdst,  bgp + k0, 16);
        cp_commit();
    }

    for (int it = 0; it < KITERS; it++) {
        cp_wait<NSTAGE - 2>();
        __syncthreads();

        {
            const int nf = it + NSTAGE - 1;
            if (nf < KITERS) {
                const int s = nf & (NSTAGE - 1);
                const int k0 = nf * BK;
                cp_async16(aS[s] + adst0, agp0 + k0, arow0_ok);
                cp_async16(aS[s] + adst1, agp1 + k0, arow1_ok);
                cp_async16(bS[s] + bdst,  bgp + k0, 16);
            }
            cp_commit();
        }

        const int s = it & (NSTAGE - 1);
        const uint32_t As = aS[s] + a_loff;
        const uint32_t Bs = bS[s] + b_loff;

        #pragma unroll
        for (int ks = 0; ks < BK; ks += 16) {
            uint32_t af[2][4], bf[4][2];
            #pragma unroll
            for (int mi = 0; mi < 2; mi++)
                ldm_x4(af[mi][0], af[mi][1], af[mi][2], af[mi][3],
                       As + (uint32_t)((mi * 16 * ASTRIDE + ks) * 2));
            #pragma unroll
            for (int p = 0; p < 2; p++)
                ldm_x4(bf[2 * p][0], bf[2 * p][1], bf[2 * p + 1][0], bf[2 * p + 1][1],
                       Bs + (uint32_t)((p * 16 * ASTRIDE + ks) * 2));
            #pragma unroll
            for (int mi = 0; mi < 2; mi++)
                #pragma unroll
                for (int ni = 0; ni < 4; ni++) {
                    float* c = acc[mi][ni];
                    asm volatile(
                        "mma.sync.aligned.m16n8k16.row.col.f32.f16.f16.f32 "
                        "{%0,%1,%2,%3}, {%4,%5,%6,%7}, {%8,%9}, {%0,%1,%2,%3};"
                        : "+f"(c[0]), "+f"(c[1]), "+f"(c[2]), "+f"(c[3])
                        : "r"(af[mi][0]), "r"(af[mi][1]), "r"(af[mi][2]), "r"(af[mi][3]),
                          "r"(bf[ni][0]), "r"(bf[ni][1]));
                }
        }
    }

    #pragma unroll
    for (int mi = 0; mi < 2; mi++) {
        const int row0 = bm + wm * 32 + mi * 16 + g;
        const int row1 = row0 + 8;
        #pragma unroll
        for (int ni = 0; ni < 4; ni++) {
            const int col = wn * 32 + ni * 8 + tc * 2;
            const float bx = sbias[col], by = sbias[col + 1];
            __half2 h0 = __floats2half2_rn(acc[mi][ni][0] + bx, acc[mi][ni][1] + by);
            __half2 h1 = __floats2half2_rn(acc[mi][ni][2] + bx, acc[mi][ni][3] + by);
            if (row0 < NN) *(__half2*)(g_AB + (size_t)row0 * CDIM + bn + col) = h0;
            if (row1 < NN) *(__half2*)(g_AB + (size_t)row1 * CDIM + bn + col) = h1;
        }
    }
}

// ---------------- phase 2: multi-edge warps, fp16 product tree, joint reductions ----------
__device__ __forceinline__ float edge_dot_h(const uint4 av, const uint4 bv,
                                            const __half2 w0, const __half2 w1,
                                            const __half2 w2, const __half2 w3,
                                            const __half2 z2) {
    __half2 a0 = *(const __half2*)&av.x, a1 = *(const __half2*)&av.y,
            a2 = *(const __half2*)&av.z, a3 = *(const __half2*)&av.w;
    __half2 b0 = *(const __half2*)&bv.x, b1 = *(const __half2*)&bv.y,
            b2 = *(const __half2*)&bv.z, b3 = *(const __half2*)&bv.w;
    // p_i = relu(a_i + b_i) * w_i, tree-summed in fp16, converted once
    __half2 s0 = __hmul2(__hmax2(__hadd2(a0, b0), z2), w0);
    s0 = __hadd2(s0, __hmul2(__hmax2(__hadd2(a1, b1), z2), w1));
    __half2 s1 = __hmul2(__hmax2(__hadd2(a2, b2), z2), w2);
    s1 = __hadd2(s1, __hmul2(__hmax2(__hadd2(a3, b3), z2), w3));
    s0 = __hadd2(s0, s1);
    float2 f = __half22float2(s0);
    return f.x + f.y;
}

__global__ __launch_bounds__(256) void edge_kernel(const long long* __restrict__ ei,
                                                   const float* __restrict__ b2,
                                                   float* __restrict__ out, int E) {
    const int lane = threadIdx.x & 31;
    const int warp = (int)(blockIdx.x * 8u + (threadIdx.x >> 5));
    const int base = warp * EPW;
    if (base >= E) return;

    // fp16 W2 slice for this lane (8 weights = 1 uint4)
    const uint4 wv = ((const uint4*)g_w2h)[lane];
    const __half2 w0 = *(const __half2*)&wv.x, w1 = *(const __half2*)&wv.y,
                  w2 = *(const __half2*)&wv.z, w3 = *(const __half2*)&wv.w;
    const __half2 z2 = __float2half2_rn(0.f);
    const float bias2 = b2[0];

    // staged byte offsets: lanes 0-7 hold r[j]*1024; lanes 8-15 hold c[j]*1024 + 512
    uint32_t myoff = 0;
    {
        const int j = lane & 7;
        const int e = base + j;
        const bool want = (lane < 16) && (e < E);
        int idx = 0;
        if (g_idx64) {
            if (want) idx = (int)ei[(lane < 8 ? (size_t)0 : (size_t)E) + e];
        } else {
            const int* p = (const int*)ei;
            if (want) idx = p[(lane < 8 ? (size_t)0 : (size_t)E) + e];
        }
        myoff = ((uint32_t)idx << 10) + (lane < 8 ? 0u : 512u);
    }
    const char* abbase = (const char*)g_AB + lane * 16;   // per-lane fixed base

    #pragma unroll
    for (int jj = 0; jj < EPW; jj += 2) {
        const int e0 = base + jj, e1 = base + jj + 1;
        const uint32_t oa0 = __shfl_sync(0xFFFFFFFFu, myoff, jj);
        const uint32_t ob0 = __shfl_sync(0xFFFFFFFFu, myoff, jj + 8);
        const uint32_t oa1 = __shfl_sync(0xFFFFFFFFu, myoff, jj + 1);
        const uint32_t ob1 = __shfl_sync(0xFFFFFFFFu, myoff, jj + 9);

        const uint4 av0 = *(const uint4*)(abbase + oa0);
        const uint4 bv0 = *(const uint4*)(abbase + ob0);
        const uint4 av1 = *(const uint4*)(abbase + oa1);
        const uint4 bv1 = *(const uint4*)(abbase + ob1);

        float acc0 = edge_dot_h(av0, bv0, w0, w1, w2, w3, z2);
        float acc1 = edge_dot_h(av1, bv1, w0, w1, w2, w3, z2);

        // joint reduction: lanes<16 carry acc0, lanes>=16 carry acc1
        float u     = (lane < 16) ? acc0 : acc1;
        float other = (lane < 16) ? acc1 : acc0;
        u += __shfl_xor_sync(0xFFFFFFFFu, other, 16);
        #pragma unroll
        for (int o = 8; o > 0; o >>= 1) u += __shfl_xor_sync(0xFFFFFFFFu, u, o);
        // lane 0 holds sum(acc0), lane 16 holds sum(acc1)

        if (lane == 0 && e0 < E)  out[e0] = 1.f / (1.f + __expf(-(u + bias2)));
        if (lane == 16 && e1 < E) out[e1] = 1.f / (1.f + __expf(-(u + bias2)));
    }
}

// ---------------- launch ----------------
extern "C" void kernel_launch(void* const* d_in, const int* in_sizes, int n_in,
                              void* d_out, int out_size) {
    const float*     x   = (const float*)d_in[0];
    const long long* ei  = (const long long*)d_in[1];
    const float*     W1  = (const float*)d_in[2];
    const float*     b1  = (const float*)d_in[3];
    const float*     W2  = (const float*)d_in[4];
    const float*     b2  = (const float*)d_in[5];
    float*           out = (float*)d_out;
    const int E = out_size;   // 320000

    prep_x_kernel<<<(XQ8 + 255) / 256, 256>>>(x);            // launch 1
    prep_w_kernel<<<(WQ8 + 255) / 256, 256>>>(W1, ei, W2);   // launch 2

    cudaFuncSetAttribute(gemm_kernel, cudaFuncAttributeMaxDynamicSharedMemorySize, SMEM_TOTAL);
    dim3 ggrid(MTILES, CDIM / BN);                            // (79, 8)
    gemm_kernel<<<ggrid, 256, SMEM_TOTAL>>>(b1);              // launch 3

    const int warps = (E + EPW - 1) / EPW;                    // 40000
    const int eblocks = (warps + 7) / 8;                      // 5000
    edge_kernel<<<eblocks, 256>>>(ei, b2, out, E);            // launch 4 (ncu capture slot)
}